// round 17
// baseline (speedup 1.0000x reference)
#include <cuda_runtime.h>
#include <cuda_bf16.h>
#include <math.h>
#include <stdint.h>

#define N_NODES 8192
#define HIDDEN  256
#define HEADS   4
#define HEAD_DIM 64
#define NUM_EDGES 4096
#define NUM_INC 65536
#define LN_EPS 1e-5f

#define LOGIT_BLOCKS 64
#define GEMM_BLOCKS  128     // 8192/64 row strips
#define AW_BLOCKS    296     // 2 per SM
#define MEGA_SMEM    83968   // 64KB ystrip + 2x9216B tiles (AW needs 64KB)

// ---------------- scratch (device globals; no allocation allowed) -------------
__device__ float    g_logit[N_NODES * HEADS];  // per-node logits
__device__ float    g_segsum[NUM_EDGES * HEADS];
__device__ float4   g_rseg[NUM_EDGES];         // valid ? 0.25/segsum : 0
__device__ int      g_ecount[NUM_EDGES];
__device__ int      g_eoffset[NUM_EDGES];
__device__ int      g_epos[NUM_EDGES];
__device__ float    g_snode[N_NODES];
__device__ int      g_cnode[N_NODES];
__device__ int      g_noffset[N_NODES];
__device__ int      g_npos[N_NODES];
__device__ int      g_sorted_node[NUM_INC];    // edge-CSR: member node ids
__device__ int      g_ne[NUM_INC];             // node-CSR: edge id per incidence
__device__ float    g_na[NUM_INC];             // node-CSR: attn_mean per incidence
__device__ int      g_done;                    // pass1 completion counter

__device__ __forceinline__ uint32_t smem_u32(const void* p) {
    uint32_t a;
    asm("{ .reg .u64 t; cvta.to.shared.u64 t, %1; cvt.u32.u64 %0, t; }"
        : "=r"(a) : "l"(p));
    return a;
}
__device__ __forceinline__ uint32_t f2tf32(float v) {
    uint32_t h;
    asm("cvt.rna.tf32.f32 %0, %1;" : "=r"(h) : "f"(v));
    return h;
}

// ---------------- K1: fused prep + logits + scratch zeroing -------------------
// blocks [0,64): compute folded u in smem, then logits for 128 nodes each.
// blocks [64,128): zero all scratch arrays.
__global__ __launch_bounds__(256) void k_front(const float* __restrict__ x,
                                               const float* __restrict__ W_w,
                                               const float* __restrict__ W_b,
                                               const float* __restrict__ edge_att) {
    if (blockIdx.x < LOGIT_BLOCKS) {
        __shared__ float  ea[HIDDEN];
        __shared__ float4 u4s[HIDDEN];
        __shared__ float  cs[HEADS];
        int t = threadIdx.x;
        ea[t] = edge_att[t];
        __syncthreads();
        float acc[HEADS];
        #pragma unroll
        for (int h = 0; h < HEADS; h++) {
            float s = 0.f;
            #pragma unroll 8
            for (int d = 0; d < HEAD_DIM; d++)
                s += W_w[(h * HEAD_DIM + d) * HIDDEN + t] * ea[h * HEAD_DIM + d];
            acc[h] = s;
        }
        u4s[t] = make_float4(acc[0], acc[1], acc[2], acc[3]);
        if (t < HEADS) {
            float s = 0.f;
            for (int d = 0; d < HEAD_DIM; d++)
                s += W_b[t * HEAD_DIM + d] * ea[t * HEAD_DIM + d];
            cs[t] = s;
        }
        __syncthreads();

        int warp = t >> 5, lane = t & 31;
        #pragma unroll 2
        for (int it = 0; it < 16; it++) {
            int node = blockIdx.x * 128 + it * 8 + warp;
            const float* xr = x + (size_t)node * HIDDEN;
            float s0 = 0.f, s1 = 0.f, s2 = 0.f, s3 = 0.f;
            #pragma unroll
            for (int tt = 0; tt < 8; tt++) {
                float xv = __ldg(xr + lane + 32 * tt);
                float4 u = u4s[lane + 32 * tt];
                s0 += xv * u.x; s1 += xv * u.y; s2 += xv * u.z; s3 += xv * u.w;
            }
            #pragma unroll
            for (int off = 16; off; off >>= 1) {
                s0 += __shfl_xor_sync(0xffffffffu, s0, off);
                s1 += __shfl_xor_sync(0xffffffffu, s1, off);
                s2 += __shfl_xor_sync(0xffffffffu, s2, off);
                s3 += __shfl_xor_sync(0xffffffffu, s3, off);
            }
            if (lane == 0)
                *(float4*)&g_logit[node * HEADS] =
                    make_float4(s0 + cs[0], s1 + cs[1], s2 + cs[2], s3 + cs[3]);
        }
    } else {
        int idx = (blockIdx.x - LOGIT_BLOCKS) * 256 + threadIdx.x;   // 0..16383
        g_segsum[idx] = 0.f;                                          // 16384
        if (idx < NUM_EDGES) { g_ecount[idx] = 0; g_epos[idx] = 0; }
        if (idx < N_NODES) { g_snode[idx] = 0.f; g_cnode[idx] = 0; g_npos[idx] = 0; }
        if (idx == 0) g_done = 0;
    }
}

// ---------------- K2: pass1 + last-block performs both scans ------------------
// Softmax shift removed: logits are bounded, exp is safe, p/segsum identical.
__global__ __launch_bounds__(256) void k_pass1s(const int* __restrict__ node_idx,
                                                const int* __restrict__ edge_idx) {
    int t = blockIdx.x * blockDim.x + threadIdx.x;   // 262144 = NUM_INC*HEADS
    {
        int i = t >> 2, h = t & 3;
        int n = node_idx[i], e = edge_idx[i];
        float l = g_logit[n * HEADS + h];
        atomicAdd(&g_segsum[e * HEADS + h], expf(l));
        if (h == 0) {
            atomicAdd(&g_ecount[e], 1);
            atomicAdd(&g_cnode[n], 1);
        }
    }
    __syncthreads();
    __shared__ int lastflag;
    if (threadIdx.x == 0) {
        __threadfence();
        lastflag = (atomicAdd(&g_done, 1) == (int)gridDim.x - 1);
    }
    __syncthreads();
    if (!lastflag) return;

    // ---- last block: edge scan (+rseg) and node scan, 256 threads ----
    int tid = threadIdx.x;
    __shared__ int sh[256];
    {   // edges: 16 per thread
        int loc[16];
        int s = 0;
        #pragma unroll
        for (int i = 0; i < 16; i++) { loc[i] = g_ecount[tid * 16 + i]; s += loc[i]; }
        sh[tid] = s;
        __syncthreads();
        for (int off = 1; off < 256; off <<= 1) {
            int add = (tid >= off) ? sh[tid - off] : 0;
            __syncthreads();
            sh[tid] += add;
            __syncthreads();
        }
        int excl = sh[tid] - s;
        #pragma unroll
        for (int i = 0; i < 16; i++) {
            int e = tid * 16 + i;
            g_eoffset[e] = excl; excl += loc[i];
            float4 r;
            if (loc[i] >= 2) {
                r.x = 0.25f / g_segsum[e * HEADS + 0];
                r.y = 0.25f / g_segsum[e * HEADS + 1];
                r.z = 0.25f / g_segsum[e * HEADS + 2];
                r.w = 0.25f / g_segsum[e * HEADS + 3];
            } else {
                r = make_float4(0.f, 0.f, 0.f, 0.f);
            }
            g_rseg[e] = r;
        }
    }
    __syncthreads();
    {   // nodes: 32 per thread
        int loc[32];
        int s = 0;
        #pragma unroll
        for (int i = 0; i < 32; i++) { loc[i] = g_cnode[tid * 32 + i]; s += loc[i]; }
        sh[tid] = s;
        __syncthreads();
        for (int off = 1; off < 256; off <<= 1) {
            int add = (tid >= off) ? sh[tid - off] : 0;
            __syncthreads();
            sh[tid] += add;
            __syncthreads();
        }
        int excl = sh[tid] - s;
        #pragma unroll
        for (int i = 0; i < 32; i++) { g_noffset[tid * 32 + i] = excl; excl += loc[i]; }
    }
}

// ---------------- K3: pass2 — attn_mean, node sums, both CSR scatters ---------
__global__ __launch_bounds__(256) void k_pass2(const int* __restrict__ node_idx,
                                               const int* __restrict__ edge_idx) {
    int i = blockIdx.x * blockDim.x + threadIdx.x;
    if (i >= NUM_INC) return;
    int n = node_idx[i], e = edge_idx[i];
    float4 l = *(const float4*)&g_logit[n * HEADS];
    float4 r = g_rseg[e];
    float am = expf(l.x) * r.x + expf(l.y) * r.y + expf(l.z) * r.z + expf(l.w) * r.w;
    atomicAdd(&g_snode[n], am);
    int pos = atomicAdd(&g_epos[e], 1);
    g_sorted_node[g_eoffset[e] + pos] = n;
    int pos2 = atomicAdd(&g_npos[n], 1);
    int nidx = g_noffset[n] + pos2;
    g_ne[nidx] = e;
    g_na[nidx] = am;
}

// ---------------- K4: mega kernel — GEMM+LN blocks ∥ persistent AW blocks -----
// blocks [0,128): tf32 MMA strip y[m0:m0+64, :] in smem (2-term compensation),
//                 then LayerNorm from smem and write `out`. No g_y round-trip.
// blocks [128,424): persistent double-buffered AW rows with TMA bulk stores.
__global__ __launch_bounds__(256) void k_mega(const float* __restrict__ X,
                                              const float* __restrict__ W,
                                              const float* __restrict__ out_b,
                                              float* __restrict__ out,
                                              float* __restrict__ AW) {
    extern __shared__ __align__(128) char smem[];
    int tid = threadIdx.x;
    int warp = tid >> 5, lane = tid & 31;

    if (blockIdx.x < GEMM_BLOCKS) {
        float (*ystrip)[HIDDEN] = (float(*)[HIDDEN])smem;             // 64x256
        float (*Xs)[36] = (float(*)[36])(smem + 65536);
        float (*Ws)[36] = (float(*)[36])(smem + 65536 + 9216);
        int m0 = blockIdx.x * 64;
        int wm = (warp & 3) >> 1 ? 32 : 0;   // warps 0..3 compute; see below
        int wn = (warp & 1) * 32;
        wm = ((warp >> 1) & 1) * 32;
        int g = lane >> 2, tg = lane & 3;

        for (int n0 = 0; n0 < HIDDEN; n0 += 64) {
            float d[2][4][4];
            #pragma unroll
            for (int i = 0; i < 2; i++)
                #pragma unroll
                for (int j = 0; j < 4; j++)
                    #pragma unroll
                    for (int q = 0; q < 4; q++) d[i][j][q] = 0.f;

            for (int kt = 0; kt < HIDDEN; kt += 32) {
                #pragma unroll
                for (int l = 0; l < 2; l++) {
                    int idx = tid + l * 256;
                    int r = idx >> 3, c = (idx & 7) * 4;
                    *(float4*)&Xs[r][c] = *(const float4*)&X[(size_t)(m0 + r) * HIDDEN + kt + c];
                    *(float4*)&Ws[r][c] = *(const float4*)&W[(size_t)(n0 + r) * HIDDEN + kt + c];
                }
                __syncthreads();
                if (warp < 4) {
                    #pragma unroll
                    for (int ks = 0; ks < 32; ks += 8) {
                        uint32_t ah[2][4], al[2][4], bh[4][2], bl[4][2];
                        #pragma unroll
                        for (int i = 0; i < 2; i++)
                            #pragma unroll
                            for (int q = 0; q < 4; q++) {
                                float v = Xs[wm + i * 16 + g + (q & 1) * 8][ks + tg + (q >> 1) * 4];
                                uint32_t h = f2tf32(v);
                                ah[i][q] = h;
                                al[i][q] = f2tf32(v - __uint_as_float(h));
                            }
                        #pragma unroll
                        for (int j = 0; j < 4; j++)
                            #pragma unroll
                            for (int q = 0; q < 2; q++) {
                                float v = Ws[wn + j * 8 + g][ks + tg + q * 4];
                                uint32_t h = f2tf32(v);
                                bh[j][q] = h;
                                bl[j][q] = f2tf32(v - __uint_as_float(h));
                            }
                        #pragma unroll
                        for (int i = 0; i < 2; i++)
                            #pragma unroll
                            for (int j = 0; j < 4; j++) {
                                float* dd = d[i][j];
                                #define MMA(AA, BB)                                              \
                                    asm volatile(                                                \
                                        "mma.sync.aligned.m16n8k8.row.col.f32.tf32.tf32.f32 "   \
                                        "{%0,%1,%2,%3},{%4,%5,%6,%7},{%8,%9},{%0,%1,%2,%3};"    \
                                        : "+f"(dd[0]), "+f"(dd[1]), "+f"(dd[2]), "+f"(dd[3])    \
                                        : "r"(AA[0]), "r"(AA[1]), "r"(AA[2]), "r"(AA[3]),       \
                                          "r"(BB[0]), "r"(BB[1]))
                                MMA(ah[i], bh[j]);
                                MMA(ah[i], bl[j]);
                                MMA(al[i], bh[j]);
                                #undef MMA
                            }
                    }
                }
                __syncthreads();
            }
            if (warp < 4) {
                #pragma unroll
                for (int i = 0; i < 2; i++)
                    #pragma unroll
                    for (int j = 0; j < 4; j++) {
                        int row = wm + i * 16 + g;
                        int col = n0 + wn + j * 8 + 2 * tg;
                        ystrip[row][col]     = d[i][j][0];
                        ystrip[row][col + 1] = d[i][j][1];
                        ystrip[row + 8][col]     = d[i][j][2];
                        ystrip[row + 8][col + 1] = d[i][j][3];
                    }
            }
            __syncthreads();
        }

        // ---- fused LayerNorm: 8 warps x 8 rows from smem ----
        #pragma unroll
        for (int r8 = 0; r8 < 8; r8++) {
            int r = warp * 8 + r8;
            int n = m0 + r;
            float alpha = g_snode[n] / fmaxf((float)g_cnode[n], 1.0f);
            float v[8];
            float s = 0.f;
            #pragma unroll
            for (int k = 0; k < 8; k++) {
                v[k] = alpha * ystrip[r][lane + 32 * k] + out_b[lane + 32 * k];
                s += v[k];
            }
            #pragma unroll
            for (int off = 16; off; off >>= 1) s += __shfl_xor_sync(0xffffffffu, s, off);
            float mu = s * (1.0f / HIDDEN);
            float s2 = 0.f;
            #pragma unroll
            for (int k = 0; k < 8; k++) { float dv = v[k] - mu; s2 += dv * dv; }
            #pragma unroll
            for (int off = 16; off; off >>= 1) s2 += __shfl_xor_sync(0xffffffffu, s2, off);
            float rstd = rsqrtf(s2 * (1.0f / HIDDEN) + LN_EPS);
            #pragma unroll
            for (int k = 0; k < 8; k++)
                out[(size_t)n * HIDDEN + lane + 32 * k] = (v[k] - mu) * rstd;
        }
        return;
    }

    // ---- persistent AW row pipeline ----
    float* b0 = (float*)smem;
    float* b1 = b0 + N_NODES;
    int abid = blockIdx.x - GEMM_BLOCKS;
    int p = 0, issued = 0;
    for (int i = abid; i < N_NODES; i += AW_BLOCKS) {
        float* row = p ? b1 : b0;
        if (tid == 0 && issued >= 2)
            asm volatile("cp.async.bulk.wait_group 1;" ::: "memory");
        __syncthreads();

        float4* r4 = (float4*)row;
        float4 z = make_float4(0.f, 0.f, 0.f, 0.f);
        #pragma unroll
        for (int t = tid; t < N_NODES / 4; t += 256) r4[t] = z;
        __syncthreads();

        int beg = g_noffset[i];
        int cnt = g_cnode[i];
        for (int k = warp; k < cnt; k += 8) {
            int e = g_ne[beg + k];
            float am = g_na[beg + k];
            if (am != 0.f) {
                int mb = g_eoffset[e], m = g_ecount[e];
                for (int t = lane; t < m; t += 32)
                    atomicAdd(&row[g_sorted_node[mb + t]], am);
            }
        }
        __syncthreads();
        if (tid == 0) {
            row[i] = 0.f;                           // zero diagonal
            asm volatile("fence.proxy.async.shared::cta;" ::: "memory");
            asm volatile(
                "cp.async.bulk.global.shared::cta.bulk_group [%0], [%1], %2;"
                :: "l"(AW + (size_t)i * N_NODES), "r"(smem_u32(row)),
                   "n"(N_NODES * 4) : "memory");
            asm volatile("cp.async.bulk.commit_group;" ::: "memory");
        }
        p ^= 1;
        issued++;
    }
    if (tid == 0)
        asm volatile("cp.async.bulk.wait_group 0;" ::: "memory");
}

// ---------------- launch ------------------------------------------------------
static bool s_init = false;

extern "C" void kernel_launch(void* const* d_in, const int* in_sizes, int n_in,
                              void* d_out, int out_size) {
    const float* x        = (const float*)d_in[0];
    const int*   node_idx = (const int*)d_in[1];
    const int*   edge_idx = (const int*)d_in[2];
    const float* W_w      = (const float*)d_in[3];
    const float* W_b      = (const float*)d_in[4];
    const float* edge_att = (const float*)d_in[5];
    const float* out_w    = (const float*)d_in[6];
    const float* out_b    = (const float*)d_in[7];

    float* out = (float*)d_out;                         // [8192, 256]
    float* AW  = out + (size_t)N_NODES * HIDDEN;        // [8192, 8192]

    if (!s_init) {
        cudaFuncSetAttribute(k_mega, cudaFuncAttributeMaxDynamicSharedMemorySize,
                             MEGA_SMEM);
        s_init = true;
    }

    k_front<<<LOGIT_BLOCKS + 64, 256>>>(x, W_w, W_b, edge_att);
    k_pass1s<<<NUM_INC * HEADS / 256, 256>>>(node_idx, edge_idx);
    k_pass2<<<NUM_INC / 256, 256>>>(node_idx, edge_idx);
    k_mega<<<GEMM_BLOCKS + AW_BLOCKS, 256, MEGA_SMEM>>>(x, out_w, out_b, out, AW);
}